// round 15
// baseline (speedup 1.0000x reference)
#include <cuda_runtime.h>
#include <cuda_fp16.h>
#include <math.h>

#define B_      8
#define IN_CH   512
#define OUT_CH  256
#define HW      64
#define OH      129
#define SPW     67
#define SP      4736
#define PLANE   4290               // 65 rows x 66 halves per (p,b,o)

// ---------------- scratch ----------------
__device__ float g_style[B_ * IN_CH];
__device__ float g_demod[B_ * OUT_CH];
__device__ float g_wsqT[IN_CH * OUT_CH];
__device__ __half g_W[(size_t)B_ * 9 * OUT_CH * IN_CH];    // [b][tap][o][i] fp16
__device__ __half g_X[(size_t)B_ * SP * IN_CH];            // [b][n][i] fp16
__device__ __half g_out1h[(size_t)4 * B_ * OUT_CH * PLANE];// [p][b][o][py][px]

// ---------------- ptx helpers ----------------
__device__ __forceinline__ unsigned su32(const void* p) {
    unsigned a;
    asm("{ .reg .u64 t; cvta.to.shared.u64 t, %1; cvt.u32.u64 %0, t; }" : "=r"(a) : "l"(p));
    return a;
}
__device__ __forceinline__ void cpa16(unsigned dst, const void* src) {
    asm volatile("cp.async.cg.shared.global [%0], [%1], 16;" :: "r"(dst), "l"(src));
}
__device__ __forceinline__ unsigned swz(unsigned x) { return x ^ ((x >> 3) & 0x70); }

__device__ __forceinline__ void ldsm4(unsigned r[4], unsigned addr) {
    asm volatile("ldmatrix.sync.aligned.m8n8.x4.shared.b16 {%0,%1,%2,%3}, [%4];"
        : "=r"(r[0]), "=r"(r[1]), "=r"(r[2]), "=r"(r[3]) : "r"(addr));
}
__device__ __forceinline__ void mma16816(float c[4], const unsigned a[4],
                                         unsigned b0, unsigned b1) {
    asm volatile(
        "mma.sync.aligned.m16n8k16.row.col.f32.f16.f16.f32 "
        "{%0,%1,%2,%3}, {%4,%5,%6,%7}, {%8,%9}, {%0,%1,%2,%3};"
        : "+f"(c[0]), "+f"(c[1]), "+f"(c[2]), "+f"(c[3])
        : "r"(a[0]), "r"(a[1]), "r"(a[2]), "r"(a[3]), "r"(b0), "r"(b1));
}

// ---------------- 0) zero-fill padded X ----------------
__global__ void xzero_kernel() {
    size_t t = (size_t)blockIdx.x * 256 + threadIdx.x;   // uint4 index
    ((uint4*)g_X)[t] = make_uint4(0, 0, 0, 0);
}

// ---------------- 1) style + wsq fused ----------------
__global__ void __launch_bounds__(512) style_wsq_kernel(const float* __restrict__ w,
                                                        const float* __restrict__ aw,
                                                        const float* __restrict__ bias,
                                                        const float* __restrict__ cw) {
    if (blockIdx.x < B_) {
        int b = blockIdx.x;
        int i = threadIdx.x;
        __shared__ float ws[IN_CH];
        ws[i] = w[b * IN_CH + i];
        __syncthreads();
        const float* ar = aw + (size_t)i * IN_CH;
        float s = 0.f;
#pragma unroll 8
        for (int l = 0; l < IN_CH; ++l) s = fmaf(ws[l], ar[l], s);
        g_style[b * IN_CH + i] = s * 0.04419417382415922f + bias[i];
    } else {
        int t = (blockIdx.x - B_) * 512 + threadIdx.x;
        int o = t & (OUT_CH - 1);
        int i = t >> 8;
        const float* p = cw + ((size_t)o * IN_CH + i) * 9;
        float s = 0.f;
#pragma unroll
        for (int k = 0; k < 9; ++k) s = fmaf(p[k], p[k], s);
        g_wsqT[i * OUT_CH + o] = s;
    }
}

// ---------------- 2) demod ----------------
__global__ void demod_kernel() {
    int b = blockIdx.x;
    int o = threadIdx.x;
    __shared__ float s2[IN_CH];
    for (int l = threadIdx.x; l < IN_CH; l += 256) {
        float v = g_style[b * IN_CH + l];
        s2[l] = v * v;
    }
    __syncthreads();
    float acc = 0.f;
#pragma unroll 4
    for (int i = 0; i < IN_CH; ++i) acc = fmaf(s2[i], g_wsqT[i * OUT_CH + o], acc);
    g_demod[b * OUT_CH + o] = rsqrtf(acc * (1.f / 4608.f) + 1e-8f);
}

// ---------------- 3) wsplit: coalesced, cw read once, loop b ----------------
__global__ void __launch_bounds__(256) wsplit_kernel(const float* __restrict__ cw) {
    const int o   = blockIdx.x;            // 256 blocks
    const int tid = threadIdx.x;
    __shared__ float sdem[B_];
    __shared__ float sstyle[B_ * IN_CH];   // 16 KB
    if (tid < B_) sdem[tid] = g_demod[tid * OUT_CH + o];
    for (int j = tid; j < B_ * IN_CH; j += 256) sstyle[j] = g_style[j];
    __syncthreads();

    float c9[2][9];
#pragma unroll
    for (int h = 0; h < 2; ++h) {
        const int i = tid + 256 * h;
        const float* p = cw + ((size_t)o * IN_CH + i) * 9;
#pragma unroll
        for (int t = 0; t < 9; ++t) c9[h][t] = p[t] * 0.014731391274719739f;
    }
#pragma unroll 1
    for (int b = 0; b < B_; ++b) {
        const float dm = sdem[b];
#pragma unroll
        for (int h = 0; h < 2; ++h) {
            const int i = tid + 256 * h;
            const float sc = sstyle[b * IN_CH + i] * dm;
#pragma unroll
            for (int t = 0; t < 9; ++t)
                g_W[(((size_t)b * 9 + t) * OUT_CH + o) * IN_CH + i] =
                    __float2half_rn(c9[h][t] * sc);
        }
    }
}

// ---------------- 4) xsplit: transpose + pad, single fp16 ----------------
__global__ void xsplit_kernel(const float* __restrict__ x) {
    __shared__ float sm[64][65];
    int icb = blockIdx.x;
    int y   = blockIdx.y;
    int b   = blockIdx.z;
    int t   = threadIdx.x;
    int xr  = t & 63, ics = t >> 6;
#pragma unroll
    for (int r = 0; r < 16; ++r) {
        int ic = ics * 16 + r;
        sm[ic][xr] = x[(((size_t)b * IN_CH + icb * 64 + ic) * HW + y) * HW + xr];
    }
    __syncthreads();
    int icw = t & 63, xs = t >> 6;
#pragma unroll
    for (int r = 0; r < 16; ++r) {
        int xc = xs + 4 * r;
        size_t idx = ((size_t)b * SP + (y + 1) * SPW + (xc + 1)) * IN_CH + icb * 64 + icw;
        g_X[idx] = __float2half_rn(sm[icw][xc]);
    }
}

// ---------------- 4b) pixel (128,128) = parity 0 plane (64,64): single-tap GEMV --
__global__ void pix_kernel(const float* __restrict__ x, const float* __restrict__ cw) {
    int b = blockIdx.x;
    int o = threadIdx.x;                 // 256
    __shared__ float xs[IN_CH];
    for (int i = threadIdx.x; i < IN_CH; i += 256)
        xs[i] = x[((size_t)(b * IN_CH + i)) * HW * HW + 63 * HW + 63]
              * g_style[b * IN_CH + i];
    __syncthreads();
    float s = 0.f;
#pragma unroll 4
    for (int i = 0; i < IN_CH; ++i)
        s = fmaf(cw[((size_t)o * IN_CH + i) * 9 + 8], xs[i], s);
    s *= 0.014731391274719739f * g_demod[b * OUT_CH + o];
    g_out1h[((size_t)b * OUT_CH + o) * PLANE + 64 * 66 + 64] = __float2half_rn(s);
}

// ---------------- 5) fused HMMA GEMM, 3-stage, fp16 planar epilogue ----------------
#define BN      256
#define WROWS   264
#define STAGES  3
#define TST     258                 // smem transpose row stride (halves)

template <int RY, int RX>
__device__ __forceinline__ void mm_body(unsigned char* dsm, int mblk, int b) {
    constexpr int NG    = (RY == 0) ? 2 : 1;
    constexpr int NKX   = (RX == 0) ? 2 : 1;
    constexpr int NJ    = NKX;
    constexpr int C     = NG * 8;
    constexpr int Py    = 65 - RY, Px = 65 - RX;
    constexpr int SPAN  = (Py - 1) * SPW + Px;
    constexpr int ABYTES = NJ * 16384;
    constexpr int BBYTES = WROWS * 128;
    constexpr int STAGE  = ABYTES + BBYTES;

    const unsigned sbase = (su32(dsm) + 1023) & ~1023u;

    const int n0 = blockIdx.x * BN;
    if (n0 >= SPAN) return;

    const int tid  = threadIdx.x;
    const int wid  = tid >> 5;
    const int lane = tid & 31;
    const int wm   = wid >> 3;
    const int wn   = wid & 7;

    auto issue = [&](int c) {
        const int g = c >> 3;
        const int q = c & 7;
        const int kh   = (RY == 0) ? 2 * g : 1;
        const int tofb = (1 - (kh >> 1)) * SPW;
        const unsigned stg = sbase + (unsigned)(c % STAGES) * STAGE;
#pragma unroll
        for (int j = 0; j < NJ; ++j) {
            const int kw = (RX == 0) ? 2 * j : 1;
            const __half* As =
                g_W + (((size_t)b * 9 + kh * 3 + kw) * OUT_CH + mblk * 128) * IN_CH + q * 64;
#pragma unroll
            for (int u = 0; u < 2; ++u) {
                int idx = tid + 512 * u;
                int row = idx >> 3, ch = idx & 7;
                cpa16(stg + j * 16384 + swz(row * 128 + ch * 16),
                      As + (size_t)row * IN_CH + ch * 8);
            }
        }
        const __half* Bs = g_X + ((size_t)b * SP + n0 + tofb) * IN_CH + q * 64;
#pragma unroll
        for (int u = 0; u < 5; ++u) {
            int idx = tid + 512 * u;
            if (idx < WROWS * 8) {
                int row = idx >> 3, ch = idx & 7;
                cpa16(stg + ABYTES + swz(row * 128 + ch * 16),
                      Bs + (size_t)row * IN_CH + ch * 8);
            }
        }
        asm volatile("cp.async.commit_group;");
    };

    float acc[4][4][4];
#pragma unroll
    for (int mi = 0; mi < 4; ++mi)
#pragma unroll
        for (int ni = 0; ni < 4; ++ni)
#pragma unroll
            for (int e = 0; e < 4; ++e) acc[mi][ni][e] = 0.f;

    issue(0);
    issue(1);

    for (int c = 0; c < C; ++c) {
        if (c + 2 < C) {
            issue(c + 2);
            asm volatile("cp.async.wait_group 2;");
        } else if (c + 2 == C) {
            asm volatile("cp.async.wait_group 1;");
        } else {
            asm volatile("cp.async.wait_group 0;");
        }
        __syncthreads();

        const unsigned As = sbase + (unsigned)(c % STAGES) * STAGE;
        const unsigned Bs = As + ABYTES;
#pragma unroll
        for (int ks = 0; ks < 4; ++ks) {
            const int chsel = ks * 2 + (lane >> 4);
#pragma unroll
            for (int j = 0; j < NJ; ++j) {
                unsigned af[4][4];
#pragma unroll
                for (int mi = 0; mi < 4; ++mi) {
                    int row = wm * 64 + mi * 16 + (lane & 15);
                    ldsm4(af[mi], As + j * 16384 + swz(row * 128 + chsel * 16));
                }
                const int dt = (RX == 0) ? (1 - j) : 1;
                unsigned bm[2][4];
#pragma unroll
                for (int nj = 0; nj < 2; ++nj) {
                    int row = dt + wn * 32 + nj * 16 + (lane & 15);
                    ldsm4(bm[nj], Bs + swz(row * 128 + chsel * 16));
                }
#pragma unroll
                for (int mi = 0; mi < 4; ++mi)
#pragma unroll
                    for (int ni = 0; ni < 4; ++ni) {
                        unsigned b0 = bm[ni >> 1][ni & 1];
                        unsigned b1 = bm[ni >> 1][(ni & 1) + 2];
                        mma16816(acc[mi][ni], af[mi], b0, b1);
                    }
            }
        }
        __syncthreads();
    }

    // ---- epilogue: smem transpose -> coalesced fp16 planar stores ----
    __half* T = (__half*)dsm;            // loop's last sync protects reuse
#pragma unroll
    for (int mi = 0; mi < 4; ++mi) {
        const int ml = wm * 64 + mi * 16 + (lane >> 2);
#pragma unroll
        for (int ni = 0; ni < 4; ++ni) {
            const int col = wn * 32 + ni * 8 + 2 * (lane & 3);
            *(__half2*)&T[ml * TST + col] =
                __floats2half2_rn(acc[mi][ni][0], acc[mi][ni][1]);
            *(__half2*)&T[(ml + 8) * TST + col] =
                __floats2half2_rn(acc[mi][ni][2], acc[mi][ni][3]);
        }
    }
    __syncthreads();

    __half* plane = g_out1h
        + (((size_t)(RY * 2 + RX) * B_ + b) * OUT_CH + mblk * 128) * PLANE;
    const int c0 = tid & 127;
    const int rg = tid >> 7;
#pragma unroll 4
    for (int k = 0; k < 32; ++k) {
        const int row = rg + 4 * k;
#pragma unroll
        for (int hh = 0; hh < 2; ++hh) {
            const int col = c0 + 128 * hh;
            const int n  = n0 + col;
            const int py = n / SPW;
            const int px = n - py * SPW;
            if (py < Py && px < Px)
                plane[(size_t)row * PLANE + py * 66 + px] = T[row * TST + col];
        }
    }
}

__global__ void __launch_bounds__(512) mm_fused() {
    extern __shared__ unsigned char dsm[];
    const int p    = blockIdx.y >> 1;
    const int mblk = blockIdx.y & 1;
    const int b    = blockIdx.z;
    switch (p) {
        case 0:  mm_body<0, 0>(dsm, mblk, b); break;
        case 1:  mm_body<0, 1>(dsm, mblk, b); break;
        case 2:  mm_body<1, 0>(dsm, mblk, b); break;
        default: mm_body<1, 1>(dsm, mblk, b); break;
    }
}

// ---------------- 6) blur: gather from fp16 parity planes ----------------
__global__ void blur_kernel(float* __restrict__ out) {
    int bo = blockIdx.z;                 // b*256 + o
    int y0 = blockIdx.y * 16;
    int x0 = blockIdx.x * 16;
    __shared__ float sm[19][20];
    int tid = threadIdx.x;
    const __half* base = g_out1h + (size_t)bo * PLANE;
    const size_t pstride = (size_t)B_ * OUT_CH * PLANE;
    for (int idx = tid; idx < 19 * 19; idx += 256) {
        int r = idx / 19, c = idx % 19;
        int Y = y0 - 1 + r, X = x0 - 1 + c;
        float v = 0.f;
        if ((unsigned)Y < 129u && (unsigned)X < 129u) {
            int p = (Y & 1) * 2 + (X & 1);
            v = __half2float(base[p * pstride + (Y >> 1) * 66 + (X >> 1)]);
        }
        sm[r][c] = v;
    }
    __syncthreads();
    int ly = tid >> 4, lx = tid & 15;
    const float cf[4] = {1.f, 3.f, 3.f, 1.f};
    float acc = 0.f;
#pragma unroll
    for (int u = 0; u < 4; ++u)
#pragma unroll
        for (int v = 0; v < 4; ++v)
            acc = fmaf(cf[u] * cf[v], sm[ly + u][lx + v], acc);
    out[(size_t)bo * 128 * 128 + (y0 + ly) * 128 + (x0 + lx)] = acc * (1.f / 16.f);
}

// ---------------- launch ----------------
extern "C" void kernel_launch(void* const* d_in, const int* in_sizes, int n_in,
                              void* d_out, int out_size) {
    const float* input = (const float*)d_in[0];
    const float* w     = (const float*)d_in[1];
    const float* aw    = (const float*)d_in[2];
    const float* bias  = (const float*)d_in[3];
    const float* cw    = (const float*)d_in[4];
    float* out = (float*)d_out;

    // max stage: NJ=2 -> 3*(2*16384 + 264*128) + 2048 = 201728 bytes
    const int S2 = STAGES * (2 * 16384 + WROWS * 128) + 2048;
    cudaFuncSetAttribute(mm_fused, cudaFuncAttributeMaxDynamicSharedMemorySize, S2);

    xzero_kernel<<<(int)(((size_t)B_ * SP * IN_CH / 8) / 256), 256>>>();
    style_wsq_kernel<<<B_ + (IN_CH * OUT_CH) / 512, 512>>>(w, aw, bias, cw);
    demod_kernel<<<B_, OUT_CH>>>();
    wsplit_kernel<<<OUT_CH, 256>>>(cw);
    xsplit_kernel<<<dim3(8, 64, B_), 256>>>(input);
    pix_kernel<<<B_, OUT_CH>>>(input, cw);
    mm_fused<<<dim3(17, 8, B_), 512, S2>>>();
    blur_kernel<<<dim3(8, 8, B_ * OUT_CH), 256>>>(out);
}

// round 16
// speedup vs baseline: 1.1456x; 1.1456x over previous
#include <cuda_runtime.h>
#include <cuda_fp16.h>
#include <math.h>

#define B_      8
#define IN_CH   512
#define OUT_CH  256
#define HW      64
#define OH      129
#define SPW     67
#define SP      4736
#define PLANE   4290               // 65 rows x 66 halves per (p,b,o)

// ---------------- scratch ----------------
__device__ float g_style[B_ * IN_CH];
__device__ float g_demod[B_ * OUT_CH];
__device__ float g_wsqT[IN_CH * OUT_CH];
__device__ __half g_W[(size_t)B_ * 9 * OUT_CH * IN_CH];    // [b][tap][o][i] fp16
__device__ __half g_X[(size_t)B_ * SP * IN_CH];            // [b][n][i] fp16
__device__ __half g_out1h[(size_t)4 * B_ * OUT_CH * PLANE];// [p][b][o][py][px]

// ---------------- ptx helpers ----------------
__device__ __forceinline__ unsigned su32(const void* p) {
    unsigned a;
    asm("{ .reg .u64 t; cvta.to.shared.u64 t, %1; cvt.u32.u64 %0, t; }" : "=r"(a) : "l"(p));
    return a;
}
__device__ __forceinline__ void cpa16(unsigned dst, const void* src) {
    asm volatile("cp.async.cg.shared.global [%0], [%1], 16;" :: "r"(dst), "l"(src));
}
__device__ __forceinline__ unsigned swz(unsigned x) { return x ^ ((x >> 3) & 0x70); }

__device__ __forceinline__ void ldsm4(unsigned r[4], unsigned addr) {
    asm volatile("ldmatrix.sync.aligned.m8n8.x4.shared.b16 {%0,%1,%2,%3}, [%4];"
        : "=r"(r[0]), "=r"(r[1]), "=r"(r[2]), "=r"(r[3]) : "r"(addr));
}
__device__ __forceinline__ void mma16816(float c[4], const unsigned a[4],
                                         unsigned b0, unsigned b1) {
    asm volatile(
        "mma.sync.aligned.m16n8k16.row.col.f32.f16.f16.f32 "
        "{%0,%1,%2,%3}, {%4,%5,%6,%7}, {%8,%9}, {%0,%1,%2,%3};"
        : "+f"(c[0]), "+f"(c[1]), "+f"(c[2]), "+f"(c[3])
        : "r"(a[0]), "r"(a[1]), "r"(a[2]), "r"(a[3]), "r"(b0), "r"(b1));
}

// ---------------- 0) zero-fill padded X ----------------
__global__ void xzero_kernel() {
    size_t t = (size_t)blockIdx.x * 256 + threadIdx.x;   // uint4 index
    ((uint4*)g_X)[t] = make_uint4(0, 0, 0, 0);
}

// ---------------- 1) style + wsq fused ----------------
__global__ void __launch_bounds__(512) style_wsq_kernel(const float* __restrict__ w,
                                                        const float* __restrict__ aw,
                                                        const float* __restrict__ bias,
                                                        const float* __restrict__ cw) {
    if (blockIdx.x < B_) {
        int b = blockIdx.x;
        int i = threadIdx.x;
        __shared__ float ws[IN_CH];
        ws[i] = w[b * IN_CH + i];
        __syncthreads();
        const float* ar = aw + (size_t)i * IN_CH;
        float s = 0.f;
#pragma unroll 8
        for (int l = 0; l < IN_CH; ++l) s = fmaf(ws[l], ar[l], s);
        g_style[b * IN_CH + i] = s * 0.04419417382415922f + bias[i];
    } else {
        int t = (blockIdx.x - B_) * 512 + threadIdx.x;
        int o = t & (OUT_CH - 1);
        int i = t >> 8;
        const float* p = cw + ((size_t)o * IN_CH + i) * 9;
        float s = 0.f;
#pragma unroll
        for (int k = 0; k < 9; ++k) s = fmaf(p[k], p[k], s);
        g_wsqT[i * OUT_CH + o] = s;
    }
}

// ---------------- 2) demod ----------------
__global__ void demod_kernel() {
    int b = blockIdx.x;
    int o = threadIdx.x;
    __shared__ float s2[IN_CH];
    for (int l = threadIdx.x; l < IN_CH; l += 256) {
        float v = g_style[b * IN_CH + l];
        s2[l] = v * v;
    }
    __syncthreads();
    float acc = 0.f;
#pragma unroll 4
    for (int i = 0; i < IN_CH; ++i) acc = fmaf(s2[i], g_wsqT[i * OUT_CH + o], acc);
    g_demod[b * OUT_CH + o] = rsqrtf(acc * (1.f / 4608.f) + 1e-8f);
}

// ---------------- 3) wsplit: coalesced, cw read once, loop b (R15-verified) -------
__global__ void __launch_bounds__(256) wsplit_kernel(const float* __restrict__ cw) {
    const int o   = blockIdx.x;            // 256 blocks
    const int tid = threadIdx.x;
    __shared__ float sdem[B_];
    __shared__ float sstyle[B_ * IN_CH];   // 16 KB
    if (tid < B_) sdem[tid] = g_demod[tid * OUT_CH + o];
    for (int j = tid; j < B_ * IN_CH; j += 256) sstyle[j] = g_style[j];
    __syncthreads();

    float c9[2][9];
#pragma unroll
    for (int h = 0; h < 2; ++h) {
        const int i = tid + 256 * h;
        const float* p = cw + ((size_t)o * IN_CH + i) * 9;
#pragma unroll
        for (int t = 0; t < 9; ++t) c9[h][t] = p[t] * 0.014731391274719739f;
    }
#pragma unroll 1
    for (int b = 0; b < B_; ++b) {
        const float dm = sdem[b];
#pragma unroll
        for (int h = 0; h < 2; ++h) {
            const int i = tid + 256 * h;
            const float sc = sstyle[b * IN_CH + i] * dm;
#pragma unroll
            for (int t = 0; t < 9; ++t)
                g_W[(((size_t)b * 9 + t) * OUT_CH + o) * IN_CH + i] =
                    __float2half_rn(c9[h][t] * sc);
        }
    }
}

// ---------------- 4) xsplit: transpose + pad, single fp16 ----------------
__global__ void xsplit_kernel(const float* __restrict__ x) {
    __shared__ float sm[64][65];
    int icb = blockIdx.x;
    int y   = blockIdx.y;
    int b   = blockIdx.z;
    int t   = threadIdx.x;
    int xr  = t & 63, ics = t >> 6;
#pragma unroll
    for (int r = 0; r < 16; ++r) {
        int ic = ics * 16 + r;
        sm[ic][xr] = x[(((size_t)b * IN_CH + icb * 64 + ic) * HW + y) * HW + xr];
    }
    __syncthreads();
    int icw = t & 63, xs = t >> 6;
#pragma unroll
    for (int r = 0; r < 16; ++r) {
        int xc = xs + 4 * r;
        size_t idx = ((size_t)b * SP + (y + 1) * SPW + (xc + 1)) * IN_CH + icb * 64 + icw;
        g_X[idx] = __float2half_rn(sm[icw][xc]);
    }
}

// ---------------- 5) fused HMMA GEMM, 2-stage, fp16 planar epilogue (R14) --------
#define BN      256
#define WROWS   264
#define STAGES  2
#define TST     258                 // smem transpose row stride (halves)

template <int RY, int RX>
__device__ __forceinline__ void mm_body(unsigned char* dsm, int mblk, int b) {
    constexpr int NG    = (RY == 0) ? 2 : 1;
    constexpr int NKX   = (RX == 0) ? 2 : 1;
    constexpr int NJ    = NKX;
    constexpr int C     = NG * 8;
    constexpr int Py    = 65 - RY, Px = 65 - RX;
    constexpr int SPAN  = (Py - 1) * SPW + Px;
    constexpr int ABYTES = NJ * 16384;
    constexpr int BBYTES = WROWS * 128;
    constexpr int STAGE  = ABYTES + BBYTES;

    const unsigned sbase = (su32(dsm) + 1023) & ~1023u;

    const int n0 = blockIdx.x * BN;
    if (n0 >= SPAN) return;

    const int tid  = threadIdx.x;
    const int wid  = tid >> 5;
    const int lane = tid & 31;
    const int wm   = wid >> 3;
    const int wn   = wid & 7;

    auto issue = [&](int c) {
        const int g = c >> 3;
        const int q = c & 7;
        const int kh   = (RY == 0) ? 2 * g : 1;
        const int tofb = (1 - (kh >> 1)) * SPW;
        const unsigned stg = sbase + (unsigned)(c % STAGES) * STAGE;
#pragma unroll
        for (int j = 0; j < NJ; ++j) {
            const int kw = (RX == 0) ? 2 * j : 1;
            const __half* As =
                g_W + (((size_t)b * 9 + kh * 3 + kw) * OUT_CH + mblk * 128) * IN_CH + q * 64;
#pragma unroll
            for (int u = 0; u < 2; ++u) {
                int idx = tid + 512 * u;
                int row = idx >> 3, ch = idx & 7;
                cpa16(stg + j * 16384 + swz(row * 128 + ch * 16),
                      As + (size_t)row * IN_CH + ch * 8);
            }
        }
        const __half* Bs = g_X + ((size_t)b * SP + n0 + tofb) * IN_CH + q * 64;
#pragma unroll
        for (int u = 0; u < 5; ++u) {
            int idx = tid + 512 * u;
            if (idx < WROWS * 8) {
                int row = idx >> 3, ch = idx & 7;
                cpa16(stg + ABYTES + swz(row * 128 + ch * 16),
                      Bs + (size_t)row * IN_CH + ch * 8);
            }
        }
        asm volatile("cp.async.commit_group;");
    };

    float acc[4][4][4];
#pragma unroll
    for (int mi = 0; mi < 4; ++mi)
#pragma unroll
        for (int ni = 0; ni < 4; ++ni)
#pragma unroll
            for (int e = 0; e < 4; ++e) acc[mi][ni][e] = 0.f;

    issue(0);

    for (int c = 0; c < C; ++c) {
        if (c + 1 < C) {
            issue(c + 1);
            asm volatile("cp.async.wait_group 1;");
        } else {
            asm volatile("cp.async.wait_group 0;");
        }
        __syncthreads();

        const unsigned As = sbase + (unsigned)(c % STAGES) * STAGE;
        const unsigned Bs = As + ABYTES;
#pragma unroll
        for (int ks = 0; ks < 4; ++ks) {
            const int chsel = ks * 2 + (lane >> 4);
#pragma unroll
            for (int j = 0; j < NJ; ++j) {
                unsigned af[4][4];
#pragma unroll
                for (int mi = 0; mi < 4; ++mi) {
                    int row = wm * 64 + mi * 16 + (lane & 15);
                    ldsm4(af[mi], As + j * 16384 + swz(row * 128 + chsel * 16));
                }
                const int dt = (RX == 0) ? (1 - j) : 1;
                unsigned bm[2][4];
#pragma unroll
                for (int nj = 0; nj < 2; ++nj) {
                    int row = dt + wn * 32 + nj * 16 + (lane & 15);
                    ldsm4(bm[nj], Bs + swz(row * 128 + chsel * 16));
                }
#pragma unroll
                for (int mi = 0; mi < 4; ++mi)
#pragma unroll
                    for (int ni = 0; ni < 4; ++ni) {
                        unsigned b0 = bm[ni >> 1][ni & 1];
                        unsigned b1 = bm[ni >> 1][(ni & 1) + 2];
                        mma16816(acc[mi][ni], af[mi], b0, b1);
                    }
            }
        }
        __syncthreads();
    }

    // ---- epilogue: smem transpose -> coalesced fp16 planar stores ----
    __half* T = (__half*)dsm;
#pragma unroll
    for (int mi = 0; mi < 4; ++mi) {
        const int ml = wm * 64 + mi * 16 + (lane >> 2);
#pragma unroll
        for (int ni = 0; ni < 4; ++ni) {
            const int col = wn * 32 + ni * 8 + 2 * (lane & 3);
            *(__half2*)&T[ml * TST + col] =
                __floats2half2_rn(acc[mi][ni][0], acc[mi][ni][1]);
            *(__half2*)&T[(ml + 8) * TST + col] =
                __floats2half2_rn(acc[mi][ni][2], acc[mi][ni][3]);
        }
    }
    __syncthreads();

    __half* plane = g_out1h
        + (((size_t)(RY * 2 + RX) * B_ + b) * OUT_CH + mblk * 128) * PLANE;
    const int c0 = tid & 127;
    const int rg = tid >> 7;
#pragma unroll 4
    for (int k = 0; k < 32; ++k) {
        const int row = rg + 4 * k;
#pragma unroll
        for (int hh = 0; hh < 2; ++hh) {
            const int col = c0 + 128 * hh;
            const int n  = n0 + col;
            const int py = n / SPW;
            const int px = n - py * SPW;
            if (py < Py && px < Px)
                plane[(size_t)row * PLANE + py * 66 + px] = T[row * TST + col];
        }
    }
}

__global__ void __launch_bounds__(512) mm_fused() {
    extern __shared__ unsigned char dsm[];
    const int p    = blockIdx.y >> 1;
    const int mblk = blockIdx.y & 1;
    const int b    = blockIdx.z;
    switch (p) {
        case 0:  mm_body<0, 0>(dsm, mblk, b); break;
        case 1:  mm_body<0, 1>(dsm, mblk, b); break;
        case 2:  mm_body<1, 0>(dsm, mblk, b); break;
        default: mm_body<1, 1>(dsm, mblk, b); break;
    }
}

// ---------------- 6) blur: gather from fp16 parity planes ----------------
__global__ void blur_kernel(float* __restrict__ out) {
    int bo = blockIdx.z;                 // b*256 + o
    int y0 = blockIdx.y * 16;
    int x0 = blockIdx.x * 16;
    __shared__ float sm[19][20];
    int tid = threadIdx.x;
    const __half* base = g_out1h + (size_t)bo * PLANE;
    const size_t pstride = (size_t)B_ * OUT_CH * PLANE;
    for (int idx = tid; idx < 19 * 19; idx += 256) {
        int r = idx / 19, c = idx % 19;
        int Y = y0 - 1 + r, X = x0 - 1 + c;
        float v = 0.f;
        if ((unsigned)Y < 129u && (unsigned)X < 129u) {
            int p = (Y & 1) * 2 + (X & 1);
            v = __half2float(base[p * pstride + (Y >> 1) * 66 + (X >> 1)]);
        }
        sm[r][c] = v;
    }
    __syncthreads();
    int ly = tid >> 4, lx = tid & 15;
    const float cf[4] = {1.f, 3.f, 3.f, 1.f};
    float acc = 0.f;
#pragma unroll
    for (int u = 0; u < 4; ++u)
#pragma unroll
        for (int v = 0; v < 4; ++v)
            acc = fmaf(cf[u] * cf[v], sm[ly + u][lx + v], acc);
    out[(size_t)bo * 128 * 128 + (y0 + ly) * 128 + (x0 + lx)] = acc * (1.f / 16.f);
}

// ---------------- launch ----------------
extern "C" void kernel_launch(void* const* d_in, const int* in_sizes, int n_in,
                              void* d_out, int out_size) {
    const float* input = (const float*)d_in[0];
    const float* w     = (const float*)d_in[1];
    const float* aw    = (const float*)d_in[2];
    const float* bias  = (const float*)d_in[3];
    const float* cw    = (const float*)d_in[4];
    float* out = (float*)d_out;

    // max stage: NJ=2 -> 2*(2*16384 + 264*128) + 2048 = 135168 bytes
    const int S2 = STAGES * (2 * 16384 + WROWS * 128) + 2048;
    cudaFuncSetAttribute(mm_fused, cudaFuncAttributeMaxDynamicSharedMemorySize, S2);

    xzero_kernel<<<(int)(((size_t)B_ * SP * IN_CH / 8) / 256), 256>>>();
    style_wsq_kernel<<<B_ + (IN_CH * OUT_CH) / 512, 512>>>(w, aw, bias, cw);
    demod_kernel<<<B_, OUT_CH>>>();
    wsplit_kernel<<<OUT_CH, 256>>>(cw);
    xsplit_kernel<<<dim3(8, 64, B_), 256>>>(input);
    mm_fused<<<dim3(18, 8, B_), 512, S2>>>();
    blur_kernel<<<dim3(8, 8, B_ * OUT_CH), 256>>>(out);
}

// round 17
// speedup vs baseline: 1.1963x; 1.0443x over previous
#include <cuda_runtime.h>
#include <cuda_fp16.h>
#include <math.h>

#define B_      8
#define IN_CH   512
#define OUT_CH  256
#define HW      64
#define OH      129
#define SPW     67
#define SP      4736
#define PLANE   4290               // 65 rows x 66 halves per (p,b,o)

// ---------------- scratch ----------------
__device__ float g_style[B_ * IN_CH];
__device__ float g_demod[B_ * OUT_CH];
__device__ float g_wsqT[IN_CH * OUT_CH];
__device__ __half g_W[(size_t)B_ * 9 * OUT_CH * IN_CH];    // [b][tap][o][i] fp16
__device__ __half g_X[(size_t)B_ * SP * IN_CH];            // [b][n][i] fp16
__device__ __half g_out1h[(size_t)4 * B_ * OUT_CH * PLANE];// [p][b][o][py][px]

// ---------------- ptx helpers ----------------
__device__ __forceinline__ unsigned su32(const void* p) {
    unsigned a;
    asm("{ .reg .u64 t; cvta.to.shared.u64 t, %1; cvt.u32.u64 %0, t; }" : "=r"(a) : "l"(p));
    return a;
}
__device__ __forceinline__ void cpa16(unsigned dst, const void* src) {
    asm volatile("cp.async.cg.shared.global [%0], [%1], 16;" :: "r"(dst), "l"(src));
}
__device__ __forceinline__ unsigned swz(unsigned x) { return x ^ ((x >> 3) & 0x70); }

__device__ __forceinline__ void ldsm4(unsigned r[4], unsigned addr) {
    asm volatile("ldmatrix.sync.aligned.m8n8.x4.shared.b16 {%0,%1,%2,%3}, [%4];"
        : "=r"(r[0]), "=r"(r[1]), "=r"(r[2]), "=r"(r[3]) : "r"(addr));
}
__device__ __forceinline__ void mma16816(float c[4], const unsigned a[4],
                                         unsigned b0, unsigned b1) {
    asm volatile(
        "mma.sync.aligned.m16n8k16.row.col.f32.f16.f16.f32 "
        "{%0,%1,%2,%3}, {%4,%5,%6,%7}, {%8,%9}, {%0,%1,%2,%3};"
        : "+f"(c[0]), "+f"(c[1]), "+f"(c[2]), "+f"(c[3])
        : "r"(a[0]), "r"(a[1]), "r"(a[2]), "r"(a[3]), "r"(b0), "r"(b1));
}

// ---------------- 0) zero-fill padded X ----------------
__global__ void xzero_kernel() {
    size_t t = (size_t)blockIdx.x * 256 + threadIdx.x;   // uint4 index
    ((uint4*)g_X)[t] = make_uint4(0, 0, 0, 0);
}

// ---------------- 1) style + wsq fused ----------------
__global__ void __launch_bounds__(512) style_wsq_kernel(const float* __restrict__ w,
                                                        const float* __restrict__ aw,
                                                        const float* __restrict__ bias,
                                                        const float* __restrict__ cw) {
    if (blockIdx.x < B_) {
        int b = blockIdx.x;
        int i = threadIdx.x;
        __shared__ float ws[IN_CH];
        ws[i] = w[b * IN_CH + i];
        __syncthreads();
        const float* ar = aw + (size_t)i * IN_CH;
        float s = 0.f;
#pragma unroll 8
        for (int l = 0; l < IN_CH; ++l) s = fmaf(ws[l], ar[l], s);
        g_style[b * IN_CH + i] = s * 0.04419417382415922f + bias[i];
    } else {
        int t = (blockIdx.x - B_) * 512 + threadIdx.x;
        int o = t & (OUT_CH - 1);
        int i = t >> 8;
        const float* p = cw + ((size_t)o * IN_CH + i) * 9;
        float s = 0.f;
#pragma unroll
        for (int k = 0; k < 9; ++k) s = fmaf(p[k], p[k], s);
        g_wsqT[i * OUT_CH + o] = s;
    }
}

// ---------------- 2) demod ----------------
__global__ void demod_kernel() {
    int b = blockIdx.x;
    int o = threadIdx.x;
    __shared__ float s2[IN_CH];
    for (int l = threadIdx.x; l < IN_CH; l += 256) {
        float v = g_style[b * IN_CH + l];
        s2[l] = v * v;
    }
    __syncthreads();
    float acc = 0.f;
#pragma unroll 4
    for (int i = 0; i < IN_CH; ++i) acc = fmaf(s2[i], g_wsqT[i * OUT_CH + o], acc);
    g_demod[b * OUT_CH + o] = rsqrtf(acc * (1.f / 4608.f) + 1e-8f);
}

// ---------------- 3) wsplit: coalesced (R15-verified) ----------------
__global__ void __launch_bounds__(256) wsplit_kernel(const float* __restrict__ cw) {
    const int o   = blockIdx.x;            // 256 blocks
    const int tid = threadIdx.x;
    __shared__ float sdem[B_];
    __shared__ float sstyle[B_ * IN_CH];
    if (tid < B_) sdem[tid] = g_demod[tid * OUT_CH + o];
    for (int j = tid; j < B_ * IN_CH; j += 256) sstyle[j] = g_style[j];
    __syncthreads();

    float c9[2][9];
#pragma unroll
    for (int h = 0; h < 2; ++h) {
        const int i = tid + 256 * h;
        const float* p = cw + ((size_t)o * IN_CH + i) * 9;
#pragma unroll
        for (int t = 0; t < 9; ++t) c9[h][t] = p[t] * 0.014731391274719739f;
    }
#pragma unroll 1
    for (int b = 0; b < B_; ++b) {
        const float dm = sdem[b];
#pragma unroll
        for (int h = 0; h < 2; ++h) {
            const int i = tid + 256 * h;
            const float sc = sstyle[b * IN_CH + i] * dm;
#pragma unroll
            for (int t = 0; t < 9; ++t)
                g_W[(((size_t)b * 9 + t) * OUT_CH + o) * IN_CH + i] =
                    __float2half_rn(c9[h][t] * sc);
        }
    }
}

// ---------------- 4) xsplit ----------------
__global__ void xsplit_kernel(const float* __restrict__ x) {
    __shared__ float sm[64][65];
    int icb = blockIdx.x;
    int y   = blockIdx.y;
    int b   = blockIdx.z;
    int t   = threadIdx.x;
    int xr  = t & 63, ics = t >> 6;
#pragma unroll
    for (int r = 0; r < 16; ++r) {
        int ic = ics * 16 + r;
        sm[ic][xr] = x[(((size_t)b * IN_CH + icb * 64 + ic) * HW + y) * HW + xr];
    }
    __syncthreads();
    int icw = t & 63, xs = t >> 6;
#pragma unroll
    for (int r = 0; r < 16; ++r) {
        int xc = xs + 4 * r;
        size_t idx = ((size_t)b * SP + (y + 1) * SPW + (xc + 1)) * IN_CH + icb * 64 + icw;
        g_X[idx] = __float2half_rn(sm[icw][xc]);
    }
}

// ---------------- 5) fused HMMA GEMM: BN=128, 256 thr, 2 CTAs/SM ----------------
#define BN      128
#define WROWS   136
#define STAGES  2
#define TST     130                 // smem transpose row stride (halves)

template <int RY, int RX>
__device__ __forceinline__ void mm_body(unsigned char* dsm, int mblk, int b) {
    constexpr int NG    = (RY == 0) ? 2 : 1;
    constexpr int NKX   = (RX == 0) ? 2 : 1;
    constexpr int NJ    = NKX;
    constexpr int C     = NG * 8;
    constexpr int Py    = 65 - RY, Px = 65 - RX;
    constexpr int SPAN  = (Py - 1) * SPW + Px;
    constexpr int ABYTES = NJ * 16384;
    constexpr int BBYTES = WROWS * 128;   // 17408
    constexpr int STAGE  = ABYTES + BBYTES;

    const unsigned sbase = (su32(dsm) + 1023) & ~1023u;

    const int n0 = blockIdx.x * BN;
    if (n0 >= SPAN) return;

    const int tid  = threadIdx.x;
    const int wid  = tid >> 5;
    const int lane = tid & 31;
    const int wm   = wid >> 2;          // 0..1 -> m offset 64
    const int wn   = wid & 3;           // 0..3 -> n offset 32

    auto issue = [&](int c) {
        const int g = c >> 3;
        const int q = c & 7;
        const int kh   = (RY == 0) ? 2 * g : 1;
        const int tofb = (1 - (kh >> 1)) * SPW;
        const unsigned stg = sbase + (unsigned)(c % STAGES) * STAGE;
#pragma unroll
        for (int j = 0; j < NJ; ++j) {
            const int kw = (RX == 0) ? 2 * j : 1;
            const __half* As =
                g_W + (((size_t)b * 9 + kh * 3 + kw) * OUT_CH + mblk * 128) * IN_CH + q * 64;
#pragma unroll
            for (int u = 0; u < 4; ++u) {
                int idx = tid + 256 * u;           // 1024 ops: 128 rows x 8 chunks
                int row = idx >> 3, ch = idx & 7;
                cpa16(stg + j * 16384 + swz(row * 128 + ch * 16),
                      As + (size_t)row * IN_CH + ch * 8);
            }
        }
        const __half* Bs = g_X + ((size_t)b * SP + n0 + tofb) * IN_CH + q * 64;
#pragma unroll
        for (int u = 0; u < 5; ++u) {
            int idx = tid + 256 * u;               // 1088 ops: 136 rows x 8 chunks
            if (idx < WROWS * 8) {
                int row = idx >> 3, ch = idx & 7;
                cpa16(stg + ABYTES + swz(row * 128 + ch * 16),
                      Bs + (size_t)row * IN_CH + ch * 8);
            }
        }
        asm volatile("cp.async.commit_group;");
    };

    float acc[4][4][4];
#pragma unroll
    for (int mi = 0; mi < 4; ++mi)
#pragma unroll
        for (int ni = 0; ni < 4; ++ni)
#pragma unroll
            for (int e = 0; e < 4; ++e) acc[mi][ni][e] = 0.f;

    issue(0);

    for (int c = 0; c < C; ++c) {
        if (c + 1 < C) {
            issue(c + 1);
            asm volatile("cp.async.wait_group 1;");
        } else {
            asm volatile("cp.async.wait_group 0;");
        }
        __syncthreads();

        const unsigned As = sbase + (unsigned)(c % STAGES) * STAGE;
        const unsigned Bs = As + ABYTES;
#pragma unroll
        for (int ks = 0; ks < 4; ++ks) {
            const int chsel = ks * 2 + (lane >> 4);
#pragma unroll
            for (int j = 0; j < NJ; ++j) {
                unsigned af[4][4];
#pragma unroll
                for (int mi = 0; mi < 4; ++mi) {
                    int row = wm * 64 + mi * 16 + (lane & 15);
                    ldsm4(af[mi], As + j * 16384 + swz(row * 128 + chsel * 16));
                }
                const int dt = (RX == 0) ? (1 - j) : 1;
                unsigned bm[2][4];
#pragma unroll
                for (int nj = 0; nj < 2; ++nj) {
                    int row = dt + wn * 32 + nj * 16 + (lane & 15);
                    ldsm4(bm[nj], Bs + swz(row * 128 + chsel * 16));
                }
#pragma unroll
                for (int mi = 0; mi < 4; ++mi)
#pragma unroll
                    for (int ni = 0; ni < 4; ++ni) {
                        unsigned b0 = bm[ni >> 1][ni & 1];
                        unsigned b1 = bm[ni >> 1][(ni & 1) + 2];
                        mma16816(acc[mi][ni], af[mi], b0, b1);
                    }
            }
        }
        __syncthreads();
    }

    // ---- epilogue: smem transpose -> coalesced fp16 planar stores ----
    __half* T = (__half*)dsm;
#pragma unroll
    for (int mi = 0; mi < 4; ++mi) {
        const int ml = wm * 64 + mi * 16 + (lane >> 2);
#pragma unroll
        for (int ni = 0; ni < 4; ++ni) {
            const int col = wn * 32 + ni * 8 + 2 * (lane & 3);
            *(__half2*)&T[ml * TST + col] =
                __floats2half2_rn(acc[mi][ni][0], acc[mi][ni][1]);
            *(__half2*)&T[(ml + 8) * TST + col] =
                __floats2half2_rn(acc[mi][ni][2], acc[mi][ni][3]);
        }
    }
    __syncthreads();

    __half* plane = g_out1h
        + (((size_t)(RY * 2 + RX) * B_ + b) * OUT_CH + mblk * 128) * PLANE;
    const int c0 = tid & 127;
    const int rg = tid >> 7;            // 2 row groups
#pragma unroll 4
    for (int k = 0; k < 64; ++k) {
        const int row = rg + 2 * k;
        const int n  = n0 + c0;
        const int py = n / SPW;
        const int px = n - py * SPW;
        if (py < Py && px < Px)
            plane[(size_t)row * PLANE + py * 66 + px] = T[row * TST + c0];
    }
}

__global__ void __launch_bounds__(256, 2) mm_fused() {
    extern __shared__ unsigned char dsm[];
    const int p    = blockIdx.y >> 1;
    const int mblk = blockIdx.y & 1;
    const int b    = blockIdx.z;
    switch (p) {
        case 0:  mm_body<0, 0>(dsm, mblk, b); break;
        case 1:  mm_body<0, 1>(dsm, mblk, b); break;
        case 2:  mm_body<1, 0>(dsm, mblk, b); break;
        default: mm_body<1, 1>(dsm, mblk, b); break;
    }
}

// ---------------- 6) blur: gather from fp16 parity planes ----------------
__global__ void blur_kernel(float* __restrict__ out) {
    int bo = blockIdx.z;                 // b*256 + o
    int y0 = blockIdx.y * 16;
    int x0 = blockIdx.x * 16;
    __shared__ float sm[19][20];
    int tid = threadIdx.x;
    const __half* base = g_out1h + (size_t)bo * PLANE;
    const size_t pstride = (size_t)B_ * OUT_CH * PLANE;
    for (int idx = tid; idx < 19 * 19; idx += 256) {
        int r = idx / 19, c = idx % 19;
        int Y = y0 - 1 + r, X = x0 - 1 + c;
        float v = 0.f;
        if ((unsigned)Y < 129u && (unsigned)X < 129u) {
            int p = (Y & 1) * 2 + (X & 1);
            v = __half2float(base[p * pstride + (Y >> 1) * 66 + (X >> 1)]);
        }
        sm[r][c] = v;
    }
    __syncthreads();
    int ly = tid >> 4, lx = tid & 15;
    const float cf[4] = {1.f, 3.f, 3.f, 1.f};
    float acc = 0.f;
#pragma unroll
    for (int u = 0; u < 4; ++u)
#pragma unroll
        for (int v = 0; v < 4; ++v)
            acc = fmaf(cf[u] * cf[v], sm[ly + u][lx + v], acc);
    out[(size_t)bo * 128 * 128 + (y0 + ly) * 128 + (x0 + lx)] = acc * (1.f / 16.f);
}

// ---------------- launch ----------------
extern "C" void kernel_launch(void* const* d_in, const int* in_sizes, int n_in,
                              void* d_out, int out_size) {
    const float* input = (const float*)d_in[0];
    const float* w     = (const float*)d_in[1];
    const float* aw    = (const float*)d_in[2];
    const float* bias  = (const float*)d_in[3];
    const float* cw    = (const float*)d_in[4];
    float* out = (float*)d_out;

    // max stage: NJ=2 -> 2*(2*16384 + 136*128) + 2048 = 102400 bytes (2 CTAs/SM)
    const int S2 = STAGES * (2 * 16384 + WROWS * 128) + 2048;
    cudaFuncSetAttribute(mm_fused, cudaFuncAttributeMaxDynamicSharedMemorySize, S2);

    xzero_kernel<<<(int)(((size_t)B_ * SP * IN_CH / 8) / 256), 256>>>();
    style_wsq_kernel<<<B_ + (IN_CH * OUT_CH) / 512, 512>>>(w, aw, bias, cw);
    demod_kernel<<<B_, OUT_CH>>>();
    wsplit_kernel<<<OUT_CH, 256>>>(cw);
    xsplit_kernel<<<dim3(8, 64, B_), 256>>>(input);
    mm_fused<<<dim3(35, 8, B_), 256, S2>>>();
    blur_kernel<<<dim3(8, 8, B_ * OUT_CH), 256>>>(out);
}